// round 15
// baseline (speedup 1.0000x reference)
#include <cuda_runtime.h>
#include <math.h>

#define NB     1805          // 5*19*19 boxes per batch
#define NBP    1824
#define NW64   29            // ceil(1805/64) u64 words per mask row
#define NW32   58
#define BPB    37            // blocks per batch
#define NBLK   (8 * BPB)     // 296 = 2/SM co-resident, >=148 (no low-grid throttle)
#define NTHR   256
#define WPB    (BPB * 8)     // warps per batch = 296
#define NCH8   228
#define NBUCK  1024          // value buckets: min(1023, key*256)

// decoded boxes (indexed by rank): corners packed, w/h packed
__device__ float4 g_box4[8][NBP];                        // x1,x2,y1,y2
__device__ float2 g_bwh [8][NBP];                        // w,h
__device__ unsigned long long g_mask[8ULL * NB * NW64];  // zero-init
__device__ unsigned long long g_intra[8][NCH8];          // 8x8 intra-chunk bytes
__device__ unsigned long long g_gtm[8][50][NW64];
__device__ int      g_part[8][3];
__device__ int      g_ticket = 0;
__device__ unsigned g_relA[8], g_cntA[8];
__device__ unsigned g_cntB[8];

__constant__ float ANCW[5] = {1.3221f, 3.19275f, 5.05587f, 9.47112f, 11.2364f};
__constant__ float ANCH[5] = {1.73145f, 4.00944f, 8.09892f, 4.84053f, 10.0071f};

// Division-free IoU > thr (carea > thr*uarea), explicit RN ops.
// Verified rel_err == 0.0 on this fixed dataset (R4, R14).
__device__ __forceinline__ bool iou_gt(
    float ax1, float ax2, float ay1, float ay2, float aw, float ah,
    float bx1, float bx2, float by1, float by2, float bw, float bh, float thr) {
    float uw = __fsub_rn(fmaxf(ax2, bx2), fminf(ax1, bx1));
    float uh = __fsub_rn(fmaxf(ay2, by2), fminf(ay1, by1));
    float cw = __fsub_rn(__fadd_rn(aw, bw), uw);
    float ch = __fsub_rn(__fadd_rn(ah, bh), uh);
    float carea = (cw > 0.0f && ch > 0.0f) ? __fmul_rn(cw, ch) : 0.0f;
    float uarea = __fsub_rn(__fadd_rn(__fmul_rn(aw, ah), __fmul_rn(bw, bh)), carea);
    return carea > __fmul_rn(thr, uarea);
}

__device__ __forceinline__ unsigned key_bucket(unsigned kbits) {
    float kf = __uint_as_float(kbits);
    unsigned bu = (unsigned)__fmul_rn(kf, 256.0f);
    return bu > 1023u ? 1023u : bu;          // monotone in key value
}

extern "C" __global__ void __launch_bounds__(NTHR, 2)
fused_kernel(const float* __restrict__ out,    // [8,125,19,19]
             const float* __restrict__ tgt,    // [8,250]
             float* __restrict__ outp)         // [6]
{
    __shared__ unsigned hist[NBUCK];           // counts -> global desc-CDF base
    __shared__ unsigned cnt [NBUCK];           // scatter cursors / bucket sizes
    __shared__ unsigned spart[NTHR];           // per-segment totals -> scan
    __shared__ unsigned long long sgrp[NBP];   // bucket-grouped (key||NB-idx)
    __shared__ float sg[252];
    __shared__ unsigned long long skeep[32];
    __shared__ unsigned long long sGV;
    __shared__ int sM, sTot, sProp, sCorr, sLast;

    const int blk = blockIdx.x;          // 0..295
    const int tid = threadIdx.x;
    const int lane = tid & 31, warp = tid >> 5;
    const int b = blk / BPB, k = blk - b * BPB;

    volatile unsigned* relA = (volatile unsigned*)&g_relA[b];
    const unsigned r0a = *relA;          // capture at entry (replay-safe)

    // ================= Phase A: 1-pass counting-sort rank + decode =======
    {
        const float* ob = out + (size_t)b * 125 * 361;
        for (int i = tid; i < NBUCK; i += NTHR) { hist[i] = 0; cnt[i] = 0; }
        if (tid < 250) sg[tid] = tgt[b * 250 + tid];

        // single global pass: keys into registers
        unsigned kb[8];
        #pragma unroll
        for (int it = 0; it < 8; it++) {
            int r = it * NTHR + tid;
            kb[it] = 0;
            if (r < NB) {
                int a = r / 361, rem = r - a * 361;
                float kk = ob[(a * 25 + 4) * 361 + rem];
                if (kk > 0.0f) kb[it] = __float_as_uint(kk);   // >0 => valid
            }
        }
        __syncthreads();
        #pragma unroll
        for (int it = 0; it < 8; it++)
            if (kb[it]) atomicAdd(&hist[key_bucket(kb[it])], 1u);
        if (tid == 255) {                        // GT validity (every block)
            unsigned long long gv = 0ULL;
            int v = 1, tb = 0;
            for (int t = 0; t < 50; t++) {
                if (sg[t * 5 + 1] == 0.0f) v = 0;
                gv |= (unsigned long long)v << t; tb += v;
            }
            sGV = gv; sTot = tb;
        }
        __syncthreads();

        // in-segment exclusive suffix (4 buckets/thread)
        {
            unsigned run = 0;
            int s0 = tid * 4;
            #pragma unroll
            for (int i = 3; i >= 0; i--) {
                unsigned c = hist[s0 + i];
                hist[s0 + i] = run;
                run += c;
            }
            spart[tid] = run;
        }
        __syncthreads();
        if (warp == 0) {                         // suffix-scan of 256 partials
            unsigned v[8], run2 = 0;
            #pragma unroll
            for (int i = 7; i >= 0; i--) {
                unsigned c = spart[lane * 8 + i];
                v[i] = run2; run2 += c;
            }
            unsigned x = run2;
            #pragma unroll
            for (int off = 1; off < 32; off <<= 1) {
                unsigned y = __shfl_down_sync(0xffffffffu, x, off);
                if (lane + off < 32) x += y;
            }
            unsigned excl = x - run2;
            #pragma unroll
            for (int i = 0; i < 8; i++) spart[lane * 8 + i] = v[i] + excl;
            if (lane == 0) sM = (int)x;          // M (block-local, identical)
        }
        __syncthreads();
        // merge cross-segment base -> hist[bu] = #keys in buckets > bu
        {
            unsigned base = spart[tid];
            int s0 = tid * 4;
            #pragma unroll
            for (int i = 0; i < 4; i++) hist[s0 + i] += base;
        }
        __syncthreads();

        // scatter from registers (order within bucket irrelevant)
        #pragma unroll
        for (int it = 0; it < 8; it++) {
            if (kb[it]) {
                int r = it * NTHR + tid;
                unsigned bu = key_bucket(kb[it]);
                unsigned slot = hist[bu] + atomicAdd(&cnt[bu], 1u);
                sgrp[slot] = ((unsigned long long)kb[it] << 32) | (unsigned)(NB - r);
            }
        }
        __syncthreads();

        // rank + decode my 49 boxes (1 thread/box)
        if (tid < 49) {
            int i = k * 49 + tid;
            if (i < NB) {
                int a = i / 361, rem = i - a * 361;
                float ki = ob[(a * 25 + 4) * 361 + rem];
                if (ki > 0.0f) {
                    unsigned kbb = __float_as_uint(ki);
                    unsigned bu = key_bucket(kbb);
                    unsigned base = hist[bu];
                    unsigned c = cnt[bu];
                    unsigned long long k64 =
                        ((unsigned long long)kbb << 32) | (unsigned)(NB - i);
                    int rank = (int)base;
                    for (unsigned q = 0; q < c; q++)
                        rank += (sgrp[base + q] > k64);
                    int hh = rem / 19, ww = rem - hh * 19;
                    const float* p = ob + (a * 25) * 361 + rem;
                    float cx = (1.0f / (1.0f + expf(-p[0]))   + (float)ww) / 19.0f;
                    float cy = (1.0f / (1.0f + expf(-p[361])) + (float)hh) / 19.0f;
                    float bw = expf(p[722])  * (ANCW[a] / 19.0f);
                    float bh = expf(p[1083]) * (ANCH[a] / 19.0f);
                    g_box4[b][rank] = make_float4(cx - bw * 0.5f, cx + bw * 0.5f,
                                                  cy - bh * 0.5f, cy + bh * 0.5f);
                    g_bwh [b][rank] = make_float2(bw, bh);
                }
            }
        }
        __threadfence();
        __syncthreads();
        if (tid == 0) {
            unsigned old = atomicAdd(&g_cntA[b], 1u);
            if (old == BPB - 1) {
                g_cntA[b] = 0;
                __threadfence();
                atomicAdd(&g_relA[b], 1u);
            }
            while (*relA == r0a) __nanosleep(32);
        }
        __syncthreads();
        __threadfence();
    }

    // ================= Phase B: balanced box + GT mask tasks =============
    {
        const int M = sM;
        const int nw32 = (M + 31) >> 5;
        const int Gbox = (M + 3) >> 2;
        const int Gtot = 2 * Gbox + 26;          // paired box tasks + 13x2 GT
        unsigned* mask32 = (unsigned*)g_mask;
        unsigned* gtm32  = (unsigned*)g_gtm;
        unsigned char* intra8 = (unsigned char*)&g_intra[b][0];
        const int wq = k * 8 + warp;             // 0..295

        for (int rep = 0; rep < 2; rep++) {
            int task;
            if (rep == 0) { if (wq >= Gtot) break; task = wq; }
            else          { if (wq >= Gtot - WPB) break; task = Gtot - 1 - wq; }

            const bool isbox = task < 2 * Gbox;
            int r0 = 0, t0 = 0, par, wlo;
            float rx1[4], rx2[4], ry1[4], ry2[4], rw[4], rh[4];
            float thr;
            if (isbox) {
                int g = task >> 1; par = task & 1;
                r0 = g << 2; thr = 0.45f; wlo = r0 >> 5;
                #pragma unroll
                for (int d = 0; d < 4; d++) {
                    int ii = min(r0 + d, NBP - 1);
                    float4 B4 = g_box4[b][ii];
                    float2 WH = g_bwh [b][ii];
                    rx1[d] = B4.x; rx2[d] = B4.y; ry1[d] = B4.z; ry2[d] = B4.w;
                    rw[d] = WH.x; rh[d] = WH.y;
                }
            } else {
                int idx = task - 2 * Gbox;
                int tg = idx >> 1; par = idx & 1;
                t0 = tg << 2; thr = 0.5f; wlo = 0;
                #pragma unroll
                for (int d = 0; d < 4; d++) {
                    int t = min(t0 + d, 49);
                    float gx = sg[t * 5 + 1], gy = sg[t * 5 + 2];
                    float gw = sg[t * 5 + 3], gh = sg[t * 5 + 4];
                    rx1[d] = gx - gw * 0.5f; rx2[d] = gx + gw * 0.5f;
                    ry1[d] = gy - gh * 0.5f; ry2[d] = gy + gh * 0.5f;
                    rw[d]  = gw;             rh[d]  = gh;
                }
            }
            int w = wlo + par;
            if (w >= nw32) continue;
            float4 C4 = g_box4[b][(w << 5) + lane];
            float2 CW = g_bwh [b][(w << 5) + lane];
            while (true) {
                int wn = w + 2;
                bool more = wn < nw32;
                float4 C4n; float2 CWn;
                if (more) {                       // prefetch next column group
                    C4n = g_box4[b][(wn << 5) + lane];
                    CWn = g_bwh [b][(wn << 5) + lane];
                }
                int j = (w << 5) + lane;
                #pragma unroll
                for (int d = 0; d < 4; d++) {
                    bool sp;
                    if (isbox) {
                        int ii = r0 + d;
                        sp = (j > ii) && (j < M) && (ii < M) &&
                             iou_gt(rx1[d], rx2[d], ry1[d], ry2[d], rw[d], rh[d],
                                    C4.x, C4.y, C4.z, C4.w, CW.x, CW.y, thr);
                    } else {
                        sp = (j < M) && (t0 + d < 50) &&
                             iou_gt(rx1[d], rx2[d], ry1[d], ry2[d], rw[d], rh[d],
                                    C4.x, C4.y, C4.z, C4.w, CW.x, CW.y, thr);
                    }
                    unsigned bal = __ballot_sync(0xffffffffu, sp);
                    if (isbox) {
                        int ii = r0 + d;
                        if (lane == d && ii < M) {
                            mask32[((size_t)(b * NB + ii)) * NW32 + w] = bal;
                            if (w == wlo)        // parity 0 owns the diag word
                                intra8[ii] = (unsigned char)((bal >> (ii & 24)) & 0xFF);
                        }
                    } else {
                        int t = t0 + d;
                        if (lane == d && t < 50)
                            gtm32[((size_t)(b * 50 + t)) * NW32 + w] = bal;
                    }
                }
                if (!more) break;
                C4 = C4n; CW = CWn; w = wn;
            }
        }

        // last-arriving block of the batch executes phase C directly
        __threadfence();
        __syncthreads();
        if (tid == 0) {
            unsigned old = atomicAdd(&g_cntB[b], 1u);
            int last = (old == BPB - 1);
            if (last) g_cntB[b] = 0;             // reset for next replay
            sLast = last;
        }
        __syncthreads();
        if (!sLast) return;
        __threadfence();                          // acquire other blocks' masks
    }

    // ================= Phase C (last block of batch): chain + stats ======
    {
        const int M = sM;
        if (tid == 0) sCorr = 0;
        __syncthreads();

        if (warp == 0) {
            const unsigned long long* mb = g_mask + (size_t)b * NB * NW64;
            const unsigned long long* ib = g_intra[b];
            const bool ld = (lane < NW64);
            const int NCH = (M + 7) >> 3;
            unsigned long long removed = 0ULL;
            unsigned long long rowb[3][8], intb[3];
            #pragma unroll
            for (int ph = 0; ph < 3; ph++) {
                intb[ph] = (ph < NCH) ? ib[ph] : 0ULL;
                #pragma unroll
                for (int d = 0; d < 8; d++) {
                    int r = ph * 8 + d;
                    rowb[ph][d] = (ld && r < M) ? mb[(size_t)r * NW64 + lane] : 0ULL;
                }
            }
            for (int c0 = 0; c0 < NCH; c0 += 3) {
                #pragma unroll
                for (int ph = 0; ph < 3; ph++) {
                    int c8 = c0 + ph;
                    if (c8 < NCH) {
                        int c = c8 << 3, w0 = c >> 6, sh = c & 63;
                        unsigned long long rwv = __shfl_sync(0xffffffffu, removed, w0);
                        unsigned supp = (unsigned)((rwv >> sh) & 0xFFULL);
                        unsigned limm = (M - c >= 8) ? 0xFFu : ((1u << (M - c)) - 1u);
                        unsigned long long intra = intb[ph];
                        unsigned dec;
                        if (intra == 0ULL) {
                            dec = (~supp) & limm;
                        } else {
                            dec = 0;
                            #pragma unroll
                            for (int d = 0; d < 8; d++)
                                if (((limm >> d) & 1u) && !((supp >> d) & 1u)) {
                                    dec  |= 1u << d;
                                    supp |= (unsigned)((intra >> (8 * d)) & 0xFFULL);
                                }
                        }
                        #pragma unroll
                        for (int d = 0; d < 8; d++)
                            if ((dec >> d) & 1u) removed |= rowb[ph][d];
                        int nc = c8 + 3;
                        intb[ph] = (nc < NCH) ? ib[nc] : 0ULL;
                        #pragma unroll
                        for (int d = 0; d < 8; d++) {
                            int r = (nc << 3) + d;
                            rowb[ph][d] = (ld && r < M)
                                        ? mb[(size_t)r * NW64 + lane] : 0ULL;
                        }
                    }
                }
            }
            skeep[lane] = ld ? removed : 0ULL;
            int pc = ld ? __popcll(removed) : 0;
            #pragma unroll
            for (int o = 16; o; o >>= 1) pc += __shfl_xor_sync(0xffffffffu, pc, o);
            if (lane == 0) sProp = M - pc;
        }
        __syncthreads();

        if (tid < 50 && ((sGV >> tid) & 1ULL)) {
            const unsigned long long* gm = g_gtm[b][tid];
            bool any = false;
            #pragma unroll
            for (int w = 0; w < NW64; w++)
                any |= (gm[w] & ~skeep[w]) != 0ULL;
            if (any) atomicAdd(&sCorr, 1);
        }
        __syncthreads();

        if (tid == 0) {
            g_part[b][0] = sTot; g_part[b][1] = sProp; g_part[b][2] = sCorr;
            __threadfence();
            int tk = atomicAdd(&g_ticket, 1);
            if (tk == 7) {
                __threadfence();
                int T = 0, P = 0, C = 0;
                for (int i = 0; i < 8; i++) {
                    T += g_part[i][0]; P += g_part[i][1]; C += g_part[i][2];
                }
                float tf = (float)T, pf = (float)P, cf = (float)C;
                float prec = cf / (pf + 1e-6f);
                float rec  = cf / (tf + 1e-6f);
                float f    = 2.0f * prec * rec / (prec + rec + 1e-6f);
                outp[0] = tf; outp[1] = pf; outp[2] = cf;
                outp[3] = prec; outp[4] = rec; outp[5] = f;
                atomicExch(&g_ticket, 0);
            }
        }
    }
}

extern "C" void kernel_launch(void* const* d_in, const int* in_sizes, int n_in,
                              void* d_out, int out_size) {
    const float* output = (const float*)d_in[0];  // [8,125,19,19]
    const float* target = (const float*)d_in[1];  // [8,250]
    fused_kernel<<<NBLK, NTHR>>>(output, target, (float*)d_out);
}

// round 16
// speedup vs baseline: 1.0310x; 1.0310x over previous
#include <cuda_runtime.h>
#include <math.h>

#define NB     1805          // 5*19*19 boxes per batch
#define NBP    1824
#define NW64   29            // ceil(1805/64) u64 words per mask row
#define NW32   58
#define BPB    37            // blocks per batch
#define NBLK   (8 * BPB)     // 296 = 2/SM co-resident, >=148 (no low-grid throttle)
#define NTHR   256
#define WPB    (BPB * 8)     // warps per batch = 296
#define NCH8   228
#define NBUCK  1024          // value buckets: min(1023, key*256)

// dynamic smem: phase A view [hist 4K | cnt 4K | sgrp 14.6K], phase B view
// [sbox4 29184 | swh 14592] (aliased; phase A data dead before reuse)
#define DSM_TOT 43776

// decoded boxes (indexed by rank): corners packed, w/h packed
__device__ float4 g_box4[8][NBP];                        // x1,x2,y1,y2
__device__ float2 g_bwh [8][NBP];                        // w,h
__device__ unsigned long long g_mask[8ULL * NB * NW64];  // zero-init
__device__ unsigned long long g_intra[8][NCH8];          // 8x8 intra-chunk bytes
__device__ unsigned long long g_gtm[8][50][NW64];
__device__ int      g_part[8][3];
__device__ int      g_ticket = 0;
__device__ unsigned g_relA[8], g_cntA[8];
__device__ unsigned g_cntB[8];

__constant__ float ANCW[5] = {1.3221f, 3.19275f, 5.05587f, 9.47112f, 11.2364f};
__constant__ float ANCH[5] = {1.73145f, 4.00944f, 8.09892f, 4.84053f, 10.0071f};

// Division-free IoU > thr (carea > thr*uarea), explicit RN ops.
// Verified rel_err == 0.0 on this fixed dataset (R4, R14, R15).
__device__ __forceinline__ bool iou_gt(
    float ax1, float ax2, float ay1, float ay2, float aw, float ah,
    float bx1, float bx2, float by1, float by2, float bw, float bh, float thr) {
    float uw = __fsub_rn(fmaxf(ax2, bx2), fminf(ax1, bx1));
    float uh = __fsub_rn(fmaxf(ay2, by2), fminf(ay1, by1));
    float cw = __fsub_rn(__fadd_rn(aw, bw), uw);
    float ch = __fsub_rn(__fadd_rn(ah, bh), uh);
    float carea = (cw > 0.0f && ch > 0.0f) ? __fmul_rn(cw, ch) : 0.0f;
    float uarea = __fsub_rn(__fadd_rn(__fmul_rn(aw, ah), __fmul_rn(bw, bh)), carea);
    return carea > __fmul_rn(thr, uarea);
}

__device__ __forceinline__ unsigned key_bucket(unsigned kbits) {
    float kf = __uint_as_float(kbits);
    unsigned bu = (unsigned)__fmul_rn(kf, 256.0f);
    return bu > 1023u ? 1023u : bu;          // monotone in key value
}

extern "C" __global__ void __launch_bounds__(NTHR, 2)
fused_kernel(const float* __restrict__ out,    // [8,125,19,19]
             const float* __restrict__ tgt,    // [8,250]
             float* __restrict__ outp)         // [6]
{
    extern __shared__ char dsm[];
    unsigned*           hist  = (unsigned*)dsm;                 // [1024] (A)
    unsigned*           cnt   = (unsigned*)(dsm + 4096);        // [1024] (A)
    unsigned long long* sgrp  = (unsigned long long*)(dsm + 8192); // [1824] (A)
    float4*             sbox4 = (float4*)dsm;                   // [1824] (B)
    float2*             swh   = (float2*)(dsm + 29184);         // [1824] (B)

    __shared__ unsigned spart[NTHR];
    __shared__ float sg[252];
    __shared__ unsigned long long skeep[32];
    __shared__ unsigned long long sGV;
    __shared__ int sM, sTot, sProp, sCorr, sLast;
    __shared__ volatile int sProg;

    const int blk = blockIdx.x;          // 0..295
    const int tid = threadIdx.x;
    const int lane = tid & 31, warp = tid >> 5;
    const int b = blk / BPB, k = blk - b * BPB;

    volatile unsigned* relA = (volatile unsigned*)&g_relA[b];
    const unsigned r0a = *relA;          // capture at entry (replay-safe)

    // ================= Phase A: 1-pass counting-sort rank + decode =======
    {
        const float* ob = out + (size_t)b * 125 * 361;
        for (int i = tid; i < NBUCK; i += NTHR) { hist[i] = 0; cnt[i] = 0; }
        if (tid < 250) sg[tid] = tgt[b * 250 + tid];

        // single global pass: keys into registers
        unsigned kb[8];
        #pragma unroll
        for (int it = 0; it < 8; it++) {
            int r = it * NTHR + tid;
            kb[it] = 0;
            if (r < NB) {
                int a = r / 361, rem = r - a * 361;
                float kk = ob[(a * 25 + 4) * 361 + rem];
                if (kk > 0.0f) kb[it] = __float_as_uint(kk);   // >0 => valid
            }
        }
        __syncthreads();
        #pragma unroll
        for (int it = 0; it < 8; it++)
            if (kb[it]) atomicAdd(&hist[key_bucket(kb[it])], 1u);
        if (tid == 255) {                        // GT validity (every block)
            unsigned long long gv = 0ULL;
            int v = 1, tb = 0;
            for (int t = 0; t < 50; t++) {
                if (sg[t * 5 + 1] == 0.0f) v = 0;
                gv |= (unsigned long long)v << t; tb += v;
            }
            sGV = gv; sTot = tb;
        }
        __syncthreads();

        // in-segment exclusive suffix (4 buckets/thread)
        {
            unsigned run = 0;
            int s0 = tid * 4;
            #pragma unroll
            for (int i = 3; i >= 0; i--) {
                unsigned c = hist[s0 + i];
                hist[s0 + i] = run;
                run += c;
            }
            spart[tid] = run;
        }
        __syncthreads();
        if (warp == 0) {                         // suffix-scan of 256 partials
            unsigned v[8], run2 = 0;
            #pragma unroll
            for (int i = 7; i >= 0; i--) {
                unsigned c = spart[lane * 8 + i];
                v[i] = run2; run2 += c;
            }
            unsigned x = run2;
            #pragma unroll
            for (int off = 1; off < 32; off <<= 1) {
                unsigned y = __shfl_down_sync(0xffffffffu, x, off);
                if (lane + off < 32) x += y;
            }
            unsigned excl = x - run2;
            #pragma unroll
            for (int i = 0; i < 8; i++) spart[lane * 8 + i] = v[i] + excl;
            if (lane == 0) sM = (int)x;          // M (block-local, identical)
        }
        __syncthreads();
        // merge cross-segment base -> hist[bu] = #keys in buckets > bu
        {
            unsigned base = spart[tid];
            int s0 = tid * 4;
            #pragma unroll
            for (int i = 0; i < 4; i++) hist[s0 + i] += base;
        }
        __syncthreads();

        // scatter from registers (order within bucket irrelevant)
        #pragma unroll
        for (int it = 0; it < 8; it++) {
            if (kb[it]) {
                int r = it * NTHR + tid;
                unsigned bu = key_bucket(kb[it]);
                unsigned slot = hist[bu] + atomicAdd(&cnt[bu], 1u);
                sgrp[slot] = ((unsigned long long)kb[it] << 32) | (unsigned)(NB - r);
            }
        }
        __syncthreads();

        // rank + decode my 49 boxes (1 thread/box)
        if (tid < 49) {
            int i = k * 49 + tid;
            if (i < NB) {
                int a = i / 361, rem = i - a * 361;
                float ki = ob[(a * 25 + 4) * 361 + rem];
                if (ki > 0.0f) {
                    unsigned kbb = __float_as_uint(ki);
                    unsigned bu = key_bucket(kbb);
                    unsigned base = hist[bu];
                    unsigned c = cnt[bu];
                    unsigned long long k64 =
                        ((unsigned long long)kbb << 32) | (unsigned)(NB - i);
                    int rank = (int)base;
                    for (unsigned q = 0; q < c; q++)
                        rank += (sgrp[base + q] > k64);
                    int hh = rem / 19, ww = rem - hh * 19;
                    const float* p = ob + (a * 25) * 361 + rem;
                    float cx = (1.0f / (1.0f + expf(-p[0]))   + (float)ww) / 19.0f;
                    float cy = (1.0f / (1.0f + expf(-p[361])) + (float)hh) / 19.0f;
                    float bw = expf(p[722])  * (ANCW[a] / 19.0f);
                    float bh = expf(p[1083]) * (ANCH[a] / 19.0f);
                    g_box4[b][rank] = make_float4(cx - bw * 0.5f, cx + bw * 0.5f,
                                                  cy - bh * 0.5f, cy + bh * 0.5f);
                    g_bwh [b][rank] = make_float2(bw, bh);
                }
            }
        }
        __threadfence();
        __syncthreads();
        if (tid == 0) {
            unsigned old = atomicAdd(&g_cntA[b], 1u);
            if (old == BPB - 1) {
                g_cntA[b] = 0;
                __threadfence();
                atomicAdd(&g_relA[b], 1u);
            }
            while (*relA == r0a) __nanosleep(32);
        }
        __syncthreads();
        __threadfence();                          // acquire peer box writes

        // cache the full batch's boxes in shared (phase A smem now dead)
        for (int i = tid; i < NBP; i += NTHR) {
            sbox4[i] = g_box4[b][i];
            swh[i]   = g_bwh [b][i];
        }
        __syncthreads();
    }

    // ================= Phase B: balanced box + GT mask tasks =============
    {
        const int M = sM;
        const int nw32 = (M + 31) >> 5;
        const int Gbox = (M + 3) >> 2;
        const int Gtot = 2 * Gbox + 26;          // paired box tasks + 13x2 GT
        unsigned* mask32 = (unsigned*)g_mask;
        unsigned* gtm32  = (unsigned*)g_gtm;
        unsigned char* intra8 = (unsigned char*)&g_intra[b][0];
        const int wq = k * 8 + warp;             // 0..295

        for (int rep = 0; rep < 2; rep++) {
            int task;
            if (rep == 0) { if (wq >= Gtot) break; task = wq; }
            else          { if (wq >= Gtot - WPB) break; task = Gtot - 1 - wq; }

            const bool isbox = task < 2 * Gbox;
            int r0 = 0, t0 = 0, par, wlo;
            float rx1[4], rx2[4], ry1[4], ry2[4], rw[4], rh[4];
            float thr;
            if (isbox) {
                int g = task >> 1; par = task & 1;
                r0 = g << 2; thr = 0.45f; wlo = r0 >> 5;
                #pragma unroll
                for (int d = 0; d < 4; d++) {
                    int ii = min(r0 + d, NBP - 1);
                    float4 B4 = sbox4[ii];
                    float2 WH = swh[ii];
                    rx1[d] = B4.x; rx2[d] = B4.y; ry1[d] = B4.z; ry2[d] = B4.w;
                    rw[d] = WH.x; rh[d] = WH.y;
                }
            } else {
                int idx = task - 2 * Gbox;
                int tg = idx >> 1; par = idx & 1;
                t0 = tg << 2; thr = 0.5f; wlo = 0;
                #pragma unroll
                for (int d = 0; d < 4; d++) {
                    int t = min(t0 + d, 49);
                    float gx = sg[t * 5 + 1], gy = sg[t * 5 + 2];
                    float gw = sg[t * 5 + 3], gh = sg[t * 5 + 4];
                    rx1[d] = gx - gw * 0.5f; rx2[d] = gx + gw * 0.5f;
                    ry1[d] = gy - gh * 0.5f; ry2[d] = gy + gh * 0.5f;
                    rw[d]  = gw;             rh[d]  = gh;
                }
            }
            for (int w = wlo + par; w < nw32; w += 2) {
                int j = (w << 5) + lane;         // smem reads < NBP in-bounds
                float4 C4 = sbox4[j];
                float2 CW = swh[j];
                #pragma unroll
                for (int d = 0; d < 4; d++) {
                    bool sp;
                    if (isbox) {
                        int ii = r0 + d;
                        sp = (j > ii) && (j < M) && (ii < M) &&
                             iou_gt(rx1[d], rx2[d], ry1[d], ry2[d], rw[d], rh[d],
                                    C4.x, C4.y, C4.z, C4.w, CW.x, CW.y, thr);
                    } else {
                        sp = (j < M) && (t0 + d < 50) &&
                             iou_gt(rx1[d], rx2[d], ry1[d], ry2[d], rw[d], rh[d],
                                    C4.x, C4.y, C4.z, C4.w, CW.x, CW.y, thr);
                    }
                    unsigned bal = __ballot_sync(0xffffffffu, sp);
                    if (isbox) {
                        int ii = r0 + d;
                        if (lane == d && ii < M) {
                            mask32[((size_t)(b * NB + ii)) * NW32 + w] = bal;
                            if (w == wlo)        // parity 0 owns the diag word
                                intra8[ii] = (unsigned char)((bal >> (ii & 24)) & 0xFF);
                        }
                    } else {
                        int t = t0 + d;
                        if (lane == d && t < 50)
                            gtm32[((size_t)(b * 50 + t)) * NW32 + w] = bal;
                    }
                }
            }
        }

        // last-arriving block of the batch executes phase C directly
        __threadfence();
        __syncthreads();
        if (tid == 0) {
            unsigned old = atomicAdd(&g_cntB[b], 1u);
            int last = (old == BPB - 1);
            if (last) g_cntB[b] = 0;             // reset for next replay
            sLast = last;
        }
        __syncthreads();
        if (!sLast) return;
        __threadfence();                          // acquire other blocks' masks
    }

    // ================= Phase C (last block of batch): chain + stats ======
    {
        const int M = sM;
        const int NCH = (M + 7) >> 3;
        const int ngroups = (NCH + 2) / 3;
        if (tid == 0) { sCorr = 0; sProg = 0; }
        __syncthreads();

        if (warp == 0) {
            const unsigned long long* mb = g_mask + (size_t)b * NB * NW64;
            const unsigned long long* ib = g_intra[b];
            const bool ld = (lane < NW64);
            unsigned long long removed = 0ULL;
            unsigned long long rowb[3][8], intb[3];
            #pragma unroll
            for (int ph = 0; ph < 3; ph++) {
                intb[ph] = (ph < NCH) ? ib[ph] : 0ULL;
                #pragma unroll
                for (int d = 0; d < 8; d++) {
                    int r = ph * 8 + d;
                    rowb[ph][d] = (ld && r < M) ? mb[(size_t)r * NW64 + lane] : 0ULL;
                }
            }
            for (int c0 = 0; c0 < NCH; c0 += 3) {
                #pragma unroll
                for (int ph = 0; ph < 3; ph++) {
                    int c8 = c0 + ph;
                    if (c8 < NCH) {
                        int c = c8 << 3, w0 = c >> 6, sh = c & 63;
                        unsigned long long rwv = __shfl_sync(0xffffffffu, removed, w0);
                        unsigned supp = (unsigned)((rwv >> sh) & 0xFFULL);
                        unsigned limm = (M - c >= 8) ? 0xFFu : ((1u << (M - c)) - 1u);
                        unsigned long long intra = intb[ph];
                        unsigned dec;
                        if (intra == 0ULL) {
                            dec = (~supp) & limm;
                        } else {
                            dec = 0;
                            #pragma unroll
                            for (int d = 0; d < 8; d++)
                                if (((limm >> d) & 1u) && !((supp >> d) & 1u)) {
                                    dec  |= 1u << d;
                                    supp |= (unsigned)((intra >> (8 * d)) & 0xFFULL);
                                }
                        }
                        #pragma unroll
                        for (int d = 0; d < 8; d++)
                            if ((dec >> d) & 1u) removed |= rowb[ph][d];
                        int nc = c8 + 3;
                        intb[ph] = (nc < NCH) ? ib[nc] : 0ULL;
                        #pragma unroll
                        for (int d = 0; d < 8; d++) {
                            int r = (nc << 3) + d;
                            rowb[ph][d] = (ld && r < M)
                                        ? mb[(size_t)r * NW64 + lane] : 0ULL;
                        }
                    }
                }
                if (lane == 0) sProg = c0 / 3 + 1;   // groups consumed
            }
            skeep[lane] = ld ? removed : 0ULL;
            int pc = ld ? __popcll(removed) : 0;
            #pragma unroll
            for (int o = 16; o; o >>= 1) pc += __shfl_xor_sync(0xffffffffu, pc, o);
            if (lane == 0) { sProp = M - pc; sProg = ngroups + 64; }
        } else {
            // warps 1..7: L1-warming prefetch of mask rows ahead of the chain.
            // Pure cache hint: no data handoff, throttled by consumer progress.
            const unsigned long long* mb = g_mask + (size_t)b * NB * NW64;
            if (lane < NW64) {
                for (int g = warp - 1; g < ngroups; g += 7) {
                    while (g > sProg + 12) __nanosleep(64);
                    int rlo = g * 24, rhi = min(rlo + 24, M);
                    for (int r = rlo; r < rhi; r++) {
                        unsigned long long v;
                        asm volatile("ld.global.b64 %0, [%1];"
                                     : "=l"(v)
                                     : "l"(mb + (size_t)r * NW64 + lane)
                                     : "memory");
                        (void)v;
                    }
                }
            }
        }
        __syncthreads();

        if (tid < 50 && ((sGV >> tid) & 1ULL)) {
            const unsigned long long* gm = g_gtm[b][tid];
            bool any = false;
            #pragma unroll
            for (int w = 0; w < NW64; w++)
                any |= (gm[w] & ~skeep[w]) != 0ULL;
            if (any) atomicAdd(&sCorr, 1);
        }
        __syncthreads();

        if (tid == 0) {
            g_part[b][0] = sTot; g_part[b][1] = sProp; g_part[b][2] = sCorr;
            __threadfence();
            int tk = atomicAdd(&g_ticket, 1);
            if (tk == 7) {
                __threadfence();
                int T = 0, P = 0, C = 0;
                for (int i = 0; i < 8; i++) {
                    T += g_part[i][0]; P += g_part[i][1]; C += g_part[i][2];
                }
                float tf = (float)T, pf = (float)P, cf = (float)C;
                float prec = cf / (pf + 1e-6f);
                float rec  = cf / (tf + 1e-6f);
                float f    = 2.0f * prec * rec / (prec + rec + 1e-6f);
                outp[0] = tf; outp[1] = pf; outp[2] = cf;
                outp[3] = prec; outp[4] = rec; outp[5] = f;
                atomicExch(&g_ticket, 0);
            }
        }
    }
}

extern "C" void kernel_launch(void* const* d_in, const int* in_sizes, int n_in,
                              void* d_out, int out_size) {
    const float* output = (const float*)d_in[0];  // [8,125,19,19]
    const float* target = (const float*)d_in[1];  // [8,250]
    fused_kernel<<<NBLK, NTHR, DSM_TOT>>>(output, target, (float*)d_out);
}